// round 1
// baseline (speedup 1.0000x reference)
#include <cuda_runtime.h>
#include <math.h>

// ---------------------------------------------------------------------------
// MaskGCNDisentangle: N=2048 nodes, B=16, D=256, H=128, E=32768
//
// Pipeline (all on default stream, graph-capturable, no allocs):
//   K0 init:   deg[i] = 1 (self loop)
//   K1 count:  deg[dst[e]]++ (int atomics)
//   K2 scan:   dinv = rsqrt(deg); rowptr = exclusive scan(deg); cursor=rowptr
//   K3 fill:   CSR by dst: (src, norm=dinv[src]*dinv[dst]) per entry (+self loops)
//   K4 mlp:    x_adj = sigmoid(-(relu(xW1+b1)W2+b2)) * x          (x_conf implicit)
//   K5 agg:    per node: agg_adj = sum norm*x_adj[src]; agg_conf = sum norm*x[src] - agg_adj
//   K6 gemm:   out_adj = agg_adj@W_adj + b_adj ; out_conf = agg_conf@W_conf + b_conf
// ---------------------------------------------------------------------------

#define N_NODES 2048
#define N_EDGES 32768
#define EMBED   256
#define HIDDEN  128
#define BATCH   16
#define ROW_TOTAL (N_NODES * BATCH)       // 32768 rows of dim 256
#define VEC       (BATCH * EMBED)         // 4096 floats per node
#define TOT_E     (N_EDGES + N_NODES)     // 34816 CSR entries

// Scratch (device globals; no runtime allocation)
__device__ float g_xadj[ROW_TOTAL * EMBED];      // 33.5 MB
__device__ float g_agg_adj[ROW_TOTAL * EMBED];   // 33.5 MB
__device__ float g_agg_conf[ROW_TOTAL * EMBED];  // 33.5 MB
__device__ int   g_deg[N_NODES];
__device__ int   g_rowptr[N_NODES + 1];
__device__ int   g_cursor[N_NODES];
__device__ float g_dinv[N_NODES];
__device__ int   g_csr_src[TOT_E];
__device__ float g_csr_norm[TOT_E];

// ---------------- K0: init degree with self loop ----------------
__global__ void k_init_deg() {
    int i = blockIdx.x * blockDim.x + threadIdx.x;
    if (i < N_NODES) g_deg[i] = 1;
}

// ---------------- K1: count in-degrees ----------------
__global__ void k_count(const int* __restrict__ dst) {
    int e = blockIdx.x * blockDim.x + threadIdx.x;
    if (e < N_EDGES) atomicAdd(&g_deg[dst[e]], 1);
}

// ---------------- K2: dinv + exclusive scan (single block) ----------------
__global__ void k_scan() {
    __shared__ int buf[2][N_NODES];
    int t = threadIdx.x;  // 1024 threads
    for (int k = t; k < N_NODES; k += 1024) {
        int d = g_deg[k];
        buf[0][k] = d;
        g_dinv[k] = rsqrtf((float)d);
    }
    __syncthreads();
    int cur = 0;
    for (int off = 1; off < N_NODES; off <<= 1) {
        int nxt = cur ^ 1;
        for (int k = t; k < N_NODES; k += 1024) {
            int v = buf[cur][k];
            if (k >= off) v += buf[cur][k - off];
            buf[nxt][k] = v;
        }
        __syncthreads();
        cur = nxt;
    }
    // buf[cur] = inclusive scan
    for (int k = t; k < N_NODES; k += 1024) {
        int incl = buf[cur][k];
        int excl = incl - g_deg[k];
        g_rowptr[k + 1] = incl;
        g_cursor[k] = excl;
    }
    if (t == 0) g_rowptr[0] = 0;
}

// ---------------- K3: fill CSR ----------------
__global__ void k_fill(const int* __restrict__ src, const int* __restrict__ dst) {
    int idx = blockIdx.x * blockDim.x + threadIdx.x;
    if (idx < N_EDGES) {
        int s = src[idx];
        int d = dst[idx];
        int p = atomicAdd(&g_cursor[d], 1);
        g_csr_src[p] = s;
        g_csr_norm[p] = g_dinv[s] * g_dinv[d];
    } else if (idx < TOT_E) {
        int i = idx - N_EDGES;           // self loop
        int p = atomicAdd(&g_cursor[i], 1);
        g_csr_src[p] = i;
        float di = g_dinv[i];
        g_csr_norm[p] = di * di;
    }
}

// ---------------- K4: MLP + adjustment mask ----------------
// 16 rows per block, 128 threads (thread j owns hidden col j, output cols j & j+128)
__global__ void __launch_bounds__(128) k_mlp(
    const float* __restrict__ x,
    const float* __restrict__ w1, const float* __restrict__ b1,
    const float* __restrict__ w2, const float* __restrict__ b2)
{
    __shared__ __align__(16) float xs[16][EMBED];   // 16 KB
    __shared__ __align__(16) float hs[16][HIDDEN];  // 8 KB
    const int j = threadIdx.x;
    const long rows0 = (long)blockIdx.x * 16;

    // load 16 rows of x (1024 float4)
    const float4* xv = (const float4*)(x + rows0 * EMBED);
    float4* xsv = (float4*)&xs[0][0];
    #pragma unroll
    for (int i = 0; i < 8; i++) xsv[j + i * 128] = xv[j + i * 128];
    __syncthreads();

    // stage 1: h = relu(x @ w1 + b1), per-thread column j
    float h[16];
    {
        float b = b1[j];
        #pragma unroll
        for (int r = 0; r < 16; r++) h[r] = b;
        for (int d = 0; d < EMBED; d += 4) {
            float wa = w1[(d + 0) * HIDDEN + j];
            float wb = w1[(d + 1) * HIDDEN + j];
            float wc = w1[(d + 2) * HIDDEN + j];
            float wd = w1[(d + 3) * HIDDEN + j];
            #pragma unroll
            for (int r = 0; r < 16; r++) {
                float4 xq = *(const float4*)&xs[r][d];
                h[r] = fmaf(xq.x, wa, h[r]);
                h[r] = fmaf(xq.y, wb, h[r]);
                h[r] = fmaf(xq.z, wc, h[r]);
                h[r] = fmaf(xq.w, wd, h[r]);
            }
        }
        #pragma unroll
        for (int r = 0; r < 16; r++) hs[r][j] = fmaxf(h[r], 0.0f);
    }
    __syncthreads();

    // stage 2: z = h @ w2 + b2, columns j and j+128
    float z0[16], z1[16];
    {
        float ba = b2[j], bb = b2[j + 128];
        #pragma unroll
        for (int r = 0; r < 16; r++) { z0[r] = ba; z1[r] = bb; }
        for (int k = 0; k < HIDDEN; k += 4) {
            float wa0 = w2[(k + 0) * EMBED + j], wa1 = w2[(k + 0) * EMBED + j + 128];
            float wb0 = w2[(k + 1) * EMBED + j], wb1 = w2[(k + 1) * EMBED + j + 128];
            float wc0 = w2[(k + 2) * EMBED + j], wc1 = w2[(k + 2) * EMBED + j + 128];
            float wd0 = w2[(k + 3) * EMBED + j], wd1 = w2[(k + 3) * EMBED + j + 128];
            #pragma unroll
            for (int r = 0; r < 16; r++) {
                float4 hq = *(const float4*)&hs[r][k];
                z0[r] = fmaf(hq.x, wa0, z0[r]); z1[r] = fmaf(hq.x, wa1, z1[r]);
                z0[r] = fmaf(hq.y, wb0, z0[r]); z1[r] = fmaf(hq.y, wb1, z1[r]);
                z0[r] = fmaf(hq.z, wc0, z0[r]); z1[r] = fmaf(hq.z, wc1, z1[r]);
                z0[r] = fmaf(hq.w, wd0, z0[r]); z1[r] = fmaf(hq.w, wd1, z1[r]);
            }
        }
    }

    // mask: x_adj = sigmoid(-z) * x = x / (1 + exp(z))
    #pragma unroll
    for (int r = 0; r < 16; r++) {
        long row = rows0 + r;
        float m0 = 1.0f / (1.0f + __expf(z0[r]));
        float m1 = 1.0f / (1.0f + __expf(z1[r]));
        g_xadj[row * EMBED + j]       = m0 * xs[r][j];
        g_xadj[row * EMBED + j + 128] = m1 * xs[r][j + 128];
    }
}

// ---------------- K5: aggregation (gather-sum via CSR) ----------------
// one block per node, 256 threads, each owns 4 float4 slots of the 4096-float vector
__global__ void __launch_bounds__(256) k_agg(const float* __restrict__ x)
{
    const int n = blockIdx.x;
    const int t = threadIdx.x;
    const int beg = g_rowptr[n], end = g_rowptr[n + 1];

    float4 aadj[4], ax[4];
    #pragma unroll
    for (int i = 0; i < 4; i++) {
        aadj[i] = make_float4(0.f, 0.f, 0.f, 0.f);
        ax[i]   = make_float4(0.f, 0.f, 0.f, 0.f);
    }

    for (int e = beg; e < end; e++) {
        int s = g_csr_src[e];
        float w = g_csr_norm[e];
        const float4* pa = (const float4*)(g_xadj + (long)s * VEC);
        const float4* px = (const float4*)(x      + (long)s * VEC);
        #pragma unroll
        for (int i = 0; i < 4; i++) {
            int idx = t + i * 256;
            float4 va = pa[idx];
            float4 vx = px[idx];
            aadj[i].x = fmaf(w, va.x, aadj[i].x); ax[i].x = fmaf(w, vx.x, ax[i].x);
            aadj[i].y = fmaf(w, va.y, aadj[i].y); ax[i].y = fmaf(w, vx.y, ax[i].y);
            aadj[i].z = fmaf(w, va.z, aadj[i].z); ax[i].z = fmaf(w, vx.z, ax[i].z);
            aadj[i].w = fmaf(w, va.w, aadj[i].w); ax[i].w = fmaf(w, vx.w, ax[i].w);
        }
    }

    float4* oa = (float4*)(g_agg_adj  + (long)n * VEC);
    float4* oc = (float4*)(g_agg_conf + (long)n * VEC);
    #pragma unroll
    for (int i = 0; i < 4; i++) {
        int idx = t + i * 256;
        oa[idx] = aadj[i];
        float4 c;
        c.x = ax[i].x - aadj[i].x;
        c.y = ax[i].y - aadj[i].y;
        c.z = ax[i].z - aadj[i].z;
        c.w = ax[i].w - aadj[i].w;
        oc[idx] = c;
    }
}

// ---------------- K6: output GEMM + bias ----------------
// grid (2048, 2): y=0 -> adj branch, y=1 -> conf branch. 16 rows/block, 256 threads.
__global__ void __launch_bounds__(256) k_gemm(
    const float* __restrict__ w_adj, const float* __restrict__ b_adj,
    const float* __restrict__ w_conf, const float* __restrict__ b_conf,
    float* __restrict__ out)
{
    __shared__ __align__(16) float as[16][EMBED];   // 16 KB
    const int sel = blockIdx.y;
    const float* A = sel ? g_agg_conf : g_agg_adj;
    const float* W = sel ? w_conf : w_adj;
    const float* B = sel ? b_conf : b_adj;
    float* O = out + (long)sel * (ROW_TOTAL * EMBED);

    const int j = threadIdx.x;
    const long rows0 = (long)blockIdx.x * 16;

    const float4* av = (const float4*)(A + rows0 * EMBED);
    float4* asv = (float4*)&as[0][0];
    #pragma unroll
    for (int i = 0; i < 4; i++) asv[j + i * 256] = av[j + i * 256];
    __syncthreads();

    float acc[16];
    float b = B[j];
    #pragma unroll
    for (int r = 0; r < 16; r++) acc[r] = b;

    for (int d = 0; d < EMBED; d += 4) {
        float wa = W[(d + 0) * EMBED + j];
        float wb = W[(d + 1) * EMBED + j];
        float wc = W[(d + 2) * EMBED + j];
        float wd = W[(d + 3) * EMBED + j];
        #pragma unroll
        for (int r = 0; r < 16; r++) {
            float4 aq = *(const float4*)&as[r][d];
            acc[r] = fmaf(aq.x, wa, acc[r]);
            acc[r] = fmaf(aq.y, wb, acc[r]);
            acc[r] = fmaf(aq.z, wc, acc[r]);
            acc[r] = fmaf(aq.w, wd, acc[r]);
        }
    }

    #pragma unroll
    for (int r = 0; r < 16; r++)
        O[(rows0 + r) * EMBED + j] = acc[r];
}

// ---------------- launch ----------------
extern "C" void kernel_launch(void* const* d_in, const int* in_sizes, int n_in,
                              void* d_out, int out_size)
{
    const float* x      = (const float*)d_in[0];
    const int*   ei     = (const int*)d_in[1];     // [2, 32768]: row0 = src, row1 = dst
    const float* w1     = (const float*)d_in[2];
    const float* b1     = (const float*)d_in[3];
    const float* w2     = (const float*)d_in[4];
    const float* b2     = (const float*)d_in[5];
    const float* w_adj  = (const float*)d_in[6];
    const float* b_adj  = (const float*)d_in[7];
    const float* w_conf = (const float*)d_in[8];
    const float* b_conf = (const float*)d_in[9];
    float* out = (float*)d_out;

    const int* src = ei;
    const int* dst = ei + N_EDGES;

    k_init_deg<<<(N_NODES + 255) / 256, 256>>>();
    k_count<<<(N_EDGES + 255) / 256, 256>>>(dst);
    k_scan<<<1, 1024>>>();
    k_fill<<<(TOT_E + 255) / 256, 256>>>(src, dst);
    k_mlp<<<ROW_TOTAL / 16, 128>>>(x, w1, b1, w2, b2);
    k_agg<<<N_NODES, 256>>>(x);
    dim3 gg(ROW_TOTAL / 16, 2);
    k_gemm<<<gg, 256>>>(w_adj, b_adj, w_conf, b_conf, out);
}

// round 2
// speedup vs baseline: 1.1025x; 1.1025x over previous
#include <cuda_runtime.h>
#include <math.h>

// ---------------------------------------------------------------------------
// MaskGCNDisentangle: N=2048 nodes, B=16, D=256, H=128, E=32768
// Round 2: f32x2 packed-FMA (FFMA2) GEMM/MLP inner loops.
//   FFMA (3-reg) is half-rate on sm_10x; fma.rn.f32x2 restores full fp32 peak.
// ---------------------------------------------------------------------------

#define N_NODES 2048
#define N_EDGES 32768
#define EMBED   256
#define HIDDEN  128
#define BATCH   16
#define ROW_TOTAL (N_NODES * BATCH)       // 32768 rows of dim 256
#define VEC       (BATCH * EMBED)         // 4096 floats per node
#define TOT_E     (N_EDGES + N_NODES)     // 34816 CSR entries

typedef unsigned long long ull;

__device__ __forceinline__ ull pk2(float a, float b) {
    ull r; asm("mov.b64 %0, {%1,%2};" : "=l"(r) : "f"(a), "f"(b)); return r;
}
__device__ __forceinline__ void fma2(ull& d, ull a, ull b) {
    asm("fma.rn.f32x2 %0, %1, %2, %0;" : "+l"(d) : "l"(a), "l"(b));
}
__device__ __forceinline__ void upk2(ull v, float& a, float& b) {
    asm("mov.b64 {%0,%1}, %2;" : "=f"(a), "=f"(b) : "l"(v));
}

// Scratch (device globals; no runtime allocation)
__device__ float g_xadj[ROW_TOTAL * EMBED];      // 33.5 MB
__device__ float g_agg_adj[ROW_TOTAL * EMBED];   // 33.5 MB
__device__ float g_agg_conf[ROW_TOTAL * EMBED];  // 33.5 MB
__device__ int   g_deg[N_NODES];
__device__ int   g_rowptr[N_NODES + 1];
__device__ int   g_cursor[N_NODES];
__device__ float g_dinv[N_NODES];
__device__ int   g_csr_src[TOT_E];
__device__ float g_csr_norm[TOT_E];

// ---------------- K0: init degree with self loop ----------------
__global__ void k_init_deg() {
    int i = blockIdx.x * blockDim.x + threadIdx.x;
    if (i < N_NODES) g_deg[i] = 1;
}

// ---------------- K1: count in-degrees ----------------
__global__ void k_count(const int* __restrict__ dst) {
    int e = blockIdx.x * blockDim.x + threadIdx.x;
    if (e < N_EDGES) atomicAdd(&g_deg[dst[e]], 1);
}

// ---------------- K2: dinv + exclusive scan (single block) ----------------
__global__ void k_scan() {
    __shared__ int buf[2][N_NODES];
    int t = threadIdx.x;  // 1024 threads
    for (int k = t; k < N_NODES; k += 1024) {
        int d = g_deg[k];
        buf[0][k] = d;
        g_dinv[k] = rsqrtf((float)d);
    }
    __syncthreads();
    int cur = 0;
    for (int off = 1; off < N_NODES; off <<= 1) {
        int nxt = cur ^ 1;
        for (int k = t; k < N_NODES; k += 1024) {
            int v = buf[cur][k];
            if (k >= off) v += buf[cur][k - off];
            buf[nxt][k] = v;
        }
        __syncthreads();
        cur = nxt;
    }
    for (int k = t; k < N_NODES; k += 1024) {
        int incl = buf[cur][k];
        int excl = incl - g_deg[k];
        g_rowptr[k + 1] = incl;
        g_cursor[k] = excl;
    }
    if (t == 0) g_rowptr[0] = 0;
}

// ---------------- K3: fill CSR ----------------
__global__ void k_fill(const int* __restrict__ src, const int* __restrict__ dst) {
    int idx = blockIdx.x * blockDim.x + threadIdx.x;
    if (idx < N_EDGES) {
        int s = src[idx];
        int d = dst[idx];
        int p = atomicAdd(&g_cursor[d], 1);
        g_csr_src[p] = s;
        g_csr_norm[p] = g_dinv[s] * g_dinv[d];
    } else if (idx < TOT_E) {
        int i = idx - N_EDGES;           // self loop
        int p = atomicAdd(&g_cursor[i], 1);
        g_csr_src[p] = i;
        float di = g_dinv[i];
        g_csr_norm[p] = di * di;
    }
}

// ---------------- K4: MLP + adjustment mask (f32x2) ----------------
// 16 rows per block, 128 threads.
// Stage1: thread owns hidden cols c1..c1+3 (2 packed pairs), 4 rows (rg*4).
// Stage2: thread owns out  cols c2..c2+7 (4 packed pairs), 4 rows.
__global__ void __launch_bounds__(128) k_mlp(
    const float* __restrict__ x,
    const float* __restrict__ w1, const float* __restrict__ b1,
    const float* __restrict__ w2, const float* __restrict__ b2)
{
    __shared__ __align__(16) float xs[16][EMBED];   // 16 KB
    __shared__ __align__(16) float hs[16][HIDDEN];  // 8 KB
    const int t = threadIdx.x;
    const long rows0 = (long)blockIdx.x * 16;

    // load 16 rows of x (1024 float4)
    {
        const float4* xv = (const float4*)(x + rows0 * EMBED);
        float4* xsv = (float4*)&xs[0][0];
        #pragma unroll
        for (int i = 0; i < 8; i++) xsv[t + i * 128] = xv[t + i * 128];
    }
    __syncthreads();

    const int rg = t >> 5;           // 0..3 -> row group of 4
    const int r1 = rg * 4;
    const int c1 = (t & 31) * 4;     // hidden col base

    // ---- stage 1: h = relu(x @ w1 + b1) ----
    {
        ull acc[4][2];
        float4 bq = *(const float4*)&b1[c1];
        ull b01 = pk2(bq.x, bq.y), b23 = pk2(bq.z, bq.w);
        #pragma unroll
        for (int r = 0; r < 4; r++) { acc[r][0] = b01; acc[r][1] = b23; }

        for (int k = 0; k < EMBED; k += 4) {
            ulonglong2 w0 = *(const ulonglong2*)&w1[(k + 0) * HIDDEN + c1];
            ulonglong2 w1q = *(const ulonglong2*)&w1[(k + 1) * HIDDEN + c1];
            ulonglong2 w2q = *(const ulonglong2*)&w1[(k + 2) * HIDDEN + c1];
            ulonglong2 w3q = *(const ulonglong2*)&w1[(k + 3) * HIDDEN + c1];
            #pragma unroll
            for (int r = 0; r < 4; r++) {
                float4 aq = *(const float4*)&xs[r1 + r][k];
                ull ax = pk2(aq.x, aq.x);
                fma2(acc[r][0], ax, w0.x); fma2(acc[r][1], ax, w0.y);
                ull ay = pk2(aq.y, aq.y);
                fma2(acc[r][0], ay, w1q.x); fma2(acc[r][1], ay, w1q.y);
                ull az = pk2(aq.z, aq.z);
                fma2(acc[r][0], az, w2q.x); fma2(acc[r][1], az, w2q.y);
                ull aw = pk2(aq.w, aq.w);
                fma2(acc[r][0], aw, w3q.x); fma2(acc[r][1], aw, w3q.y);
            }
        }
        #pragma unroll
        for (int r = 0; r < 4; r++) {
            float4 h;
            upk2(acc[r][0], h.x, h.y);
            upk2(acc[r][1], h.z, h.w);
            h.x = fmaxf(h.x, 0.f); h.y = fmaxf(h.y, 0.f);
            h.z = fmaxf(h.z, 0.f); h.w = fmaxf(h.w, 0.f);
            *(float4*)&hs[r1 + r][c1] = h;
        }
    }
    __syncthreads();

    // ---- stage 2: z = h @ w2 + b2; x_adj = x / (1 + exp(z)) ----
    {
        const int c2 = (t & 31) * 8;
        ull acc[4][4];
        float4 ba = *(const float4*)&b2[c2];
        float4 bb = *(const float4*)&b2[c2 + 4];
        ull b0 = pk2(ba.x, ba.y), b1p = pk2(ba.z, ba.w);
        ull b2p = pk2(bb.x, bb.y), b3p = pk2(bb.z, bb.w);
        #pragma unroll
        for (int r = 0; r < 4; r++) {
            acc[r][0] = b0; acc[r][1] = b1p; acc[r][2] = b2p; acc[r][3] = b3p;
        }

        for (int k = 0; k < HIDDEN; k += 4) {
            ulonglong2 wq[4][2];
            #pragma unroll
            for (int i = 0; i < 4; i++) {
                wq[i][0] = *(const ulonglong2*)&w2[(k + i) * EMBED + c2];
                wq[i][1] = *(const ulonglong2*)&w2[(k + i) * EMBED + c2 + 4];
            }
            #pragma unroll
            for (int r = 0; r < 4; r++) {
                float4 hq = *(const float4*)&hs[r1 + r][k];
                ull ax = pk2(hq.x, hq.x);
                fma2(acc[r][0], ax, wq[0][0].x); fma2(acc[r][1], ax, wq[0][0].y);
                fma2(acc[r][2], ax, wq[0][1].x); fma2(acc[r][3], ax, wq[0][1].y);
                ull ay = pk2(hq.y, hq.y);
                fma2(acc[r][0], ay, wq[1][0].x); fma2(acc[r][1], ay, wq[1][0].y);
                fma2(acc[r][2], ay, wq[1][1].x); fma2(acc[r][3], ay, wq[1][1].y);
                ull az = pk2(hq.z, hq.z);
                fma2(acc[r][0], az, wq[2][0].x); fma2(acc[r][1], az, wq[2][0].y);
                fma2(acc[r][2], az, wq[2][1].x); fma2(acc[r][3], az, wq[2][1].y);
                ull aw = pk2(hq.w, hq.w);
                fma2(acc[r][0], aw, wq[3][0].x); fma2(acc[r][1], aw, wq[3][0].y);
                fma2(acc[r][2], aw, wq[3][1].x); fma2(acc[r][3], aw, wq[3][1].y);
            }
        }

        #pragma unroll
        for (int r = 0; r < 4; r++) {
            long row = rows0 + r1 + r;
            float z[8];
            upk2(acc[r][0], z[0], z[1]);
            upk2(acc[r][1], z[2], z[3]);
            upk2(acc[r][2], z[4], z[5]);
            upk2(acc[r][3], z[6], z[7]);
            float4 xa = *(const float4*)&xs[r1 + r][c2];
            float4 xb = *(const float4*)&xs[r1 + r][c2 + 4];
            float4 o0, o1;
            o0.x = xa.x / (1.0f + __expf(z[0]));
            o0.y = xa.y / (1.0f + __expf(z[1]));
            o0.z = xa.z / (1.0f + __expf(z[2]));
            o0.w = xa.w / (1.0f + __expf(z[3]));
            o1.x = xb.x / (1.0f + __expf(z[4]));
            o1.y = xb.y / (1.0f + __expf(z[5]));
            o1.z = xb.z / (1.0f + __expf(z[6]));
            o1.w = xb.w / (1.0f + __expf(z[7]));
            *(float4*)&g_xadj[row * EMBED + c2]     = o0;
            *(float4*)&g_xadj[row * EMBED + c2 + 4] = o1;
        }
    }
}

// ---------------- K5: aggregation (gather-sum via CSR) ----------------
__global__ void __launch_bounds__(256) k_agg(const float* __restrict__ x)
{
    const int n = blockIdx.x;
    const int t = threadIdx.x;
    const int beg = g_rowptr[n], end = g_rowptr[n + 1];

    float4 aadj[4], ax[4];
    #pragma unroll
    for (int i = 0; i < 4; i++) {
        aadj[i] = make_float4(0.f, 0.f, 0.f, 0.f);
        ax[i]   = make_float4(0.f, 0.f, 0.f, 0.f);
    }

    for (int e = beg; e < end; e++) {
        int s = g_csr_src[e];
        float w = g_csr_norm[e];
        const float4* pa = (const float4*)(g_xadj + (long)s * VEC);
        const float4* px = (const float4*)(x      + (long)s * VEC);
        #pragma unroll
        for (int i = 0; i < 4; i++) {
            int idx = t + i * 256;
            float4 va = pa[idx];
            float4 vx = px[idx];
            aadj[i].x = fmaf(w, va.x, aadj[i].x); ax[i].x = fmaf(w, vx.x, ax[i].x);
            aadj[i].y = fmaf(w, va.y, aadj[i].y); ax[i].y = fmaf(w, vx.y, ax[i].y);
            aadj[i].z = fmaf(w, va.z, aadj[i].z); ax[i].z = fmaf(w, vx.z, ax[i].z);
            aadj[i].w = fmaf(w, va.w, aadj[i].w); ax[i].w = fmaf(w, vx.w, ax[i].w);
        }
    }

    float4* oa = (float4*)(g_agg_adj  + (long)n * VEC);
    float4* oc = (float4*)(g_agg_conf + (long)n * VEC);
    #pragma unroll
    for (int i = 0; i < 4; i++) {
        int idx = t + i * 256;
        oa[idx] = aadj[i];
        float4 c;
        c.x = ax[i].x - aadj[i].x;
        c.y = ax[i].y - aadj[i].y;
        c.z = ax[i].z - aadj[i].z;
        c.w = ax[i].w - aadj[i].w;
        oc[idx] = c;
    }
}

// ---------------- K6: output GEMM + bias (f32x2) ----------------
// grid (1024, 2); 32 rows/block, 256 threads.
// Thread owns cols c..c+3 (2 packed pairs) x 8 rows (rg*8).
__global__ void __launch_bounds__(256) k_gemm(
    const float* __restrict__ w_adj, const float* __restrict__ b_adj,
    const float* __restrict__ w_conf, const float* __restrict__ b_conf,
    float* __restrict__ out)
{
    __shared__ __align__(16) float as[32][EMBED];   // 32 KB
    const int sel = blockIdx.y;
    const float* A = sel ? g_agg_conf : g_agg_adj;
    const float* W = sel ? w_conf : w_adj;
    const float* Bb = sel ? b_conf : b_adj;
    float* O = out + (long)sel * ((long)ROW_TOTAL * EMBED);

    const int t = threadIdx.x;
    const long rows0 = (long)blockIdx.x * 32;

    {
        const float4* av = (const float4*)(A + rows0 * EMBED);
        float4* asv = (float4*)&as[0][0];
        #pragma unroll
        for (int i = 0; i < 8; i++) asv[t + i * 256] = av[t + i * 256];
    }
    __syncthreads();

    const int c  = (t & 63) * 4;
    const int r0 = (t >> 6) * 8;

    ull acc[8][2];
    float4 bq = *(const float4*)&Bb[c];
    ull b01 = pk2(bq.x, bq.y), b23 = pk2(bq.z, bq.w);
    #pragma unroll
    for (int r = 0; r < 8; r++) { acc[r][0] = b01; acc[r][1] = b23; }

    for (int k = 0; k < EMBED; k += 4) {
        ulonglong2 w0 = *(const ulonglong2*)&W[(k + 0) * EMBED + c];
        ulonglong2 w1 = *(const ulonglong2*)&W[(k + 1) * EMBED + c];
        ulonglong2 w2 = *(const ulonglong2*)&W[(k + 2) * EMBED + c];
        ulonglong2 w3 = *(const ulonglong2*)&W[(k + 3) * EMBED + c];
        #pragma unroll
        for (int r = 0; r < 8; r++) {
            float4 aq = *(const float4*)&as[r0 + r][k];
            ull ax = pk2(aq.x, aq.x);
            fma2(acc[r][0], ax, w0.x); fma2(acc[r][1], ax, w0.y);
            ull ay = pk2(aq.y, aq.y);
            fma2(acc[r][0], ay, w1.x); fma2(acc[r][1], ay, w1.y);
            ull az = pk2(aq.z, aq.z);
            fma2(acc[r][0], az, w2.x); fma2(acc[r][1], az, w2.y);
            ull aw = pk2(aq.w, aq.w);
            fma2(acc[r][0], aw, w3.x); fma2(acc[r][1], aw, w3.y);
        }
    }

    #pragma unroll
    for (int r = 0; r < 8; r++) {
        float4 o;
        upk2(acc[r][0], o.x, o.y);
        upk2(acc[r][1], o.z, o.w);
        *(float4*)&O[(rows0 + r0 + r) * EMBED + c] = o;
    }
}

// ---------------- launch ----------------
extern "C" void kernel_launch(void* const* d_in, const int* in_sizes, int n_in,
                              void* d_out, int out_size)
{
    const float* x      = (const float*)d_in[0];
    const int*   ei     = (const int*)d_in[1];     // [2, 32768]: row0 = src, row1 = dst
    const float* w1     = (const float*)d_in[2];
    const float* b1     = (const float*)d_in[3];
    const float* w2     = (const float*)d_in[4];
    const float* b2     = (const float*)d_in[5];
    const float* w_adj  = (const float*)d_in[6];
    const float* b_adj  = (const float*)d_in[7];
    const float* w_conf = (const float*)d_in[8];
    const float* b_conf = (const float*)d_in[9];
    float* out = (float*)d_out;

    const int* src = ei;
    const int* dst = ei + N_EDGES;

    // Launch order puts k_mlp at index 3 so ncu (-s 5, ~2 harness launches
    // ahead of ours) captures the heavy MLP kernel instead of prep.
    k_init_deg<<<(N_NODES + 255) / 256, 256>>>();
    k_count<<<(N_EDGES + 255) / 256, 256>>>(dst);
    k_scan<<<1, 1024>>>();
    k_mlp<<<ROW_TOTAL / 16, 128>>>(x, w1, b1, w2, b2);
    k_fill<<<(TOT_E + 255) / 256, 256>>>(src, dst);
    k_agg<<<N_NODES, 256>>>(x);
    dim3 gg(ROW_TOTAL / 32, 2);
    k_gemm<<<gg, 256>>>(w_adj, b_adj, w_conf, b_conf, out);
}

// round 5
// speedup vs baseline: 1.2708x; 1.1526x over previous
#include <cuda_runtime.h>
#include <math.h>

// ---------------------------------------------------------------------------
// MaskGCNDisentangle — Round 5 (re-submission: rounds 3 & 4 hit broker/infra
// container-acquisition failures; kernel never executed).
// f32x2 packed-FMA matmuls with C=8 column tiles to amortize pack-movs;
// 128-thread / 32-row blocks for both matmul kernels.
// ---------------------------------------------------------------------------

#define N_NODES 2048
#define N_EDGES 32768
#define EMBED   256
#define HIDDEN  128
#define BATCH   16
#define ROW_TOTAL (N_NODES * BATCH)       // 32768 rows of dim 256
#define VEC       (BATCH * EMBED)         // 4096 floats per node
#define TOT_E     (N_EDGES + N_NODES)     // 34816 CSR entries

typedef unsigned long long ull;

__device__ __forceinline__ ull pk2(float a, float b) {
    ull r; asm("mov.b64 %0, {%1,%2};" : "=l"(r) : "f"(a), "f"(b)); return r;
}
__device__ __forceinline__ void fma2(ull& d, ull a, ull b) {
    asm("fma.rn.f32x2 %0, %1, %2, %0;" : "+l"(d) : "l"(a), "l"(b));
}
__device__ __forceinline__ void upk2(ull v, float& a, float& b) {
    asm("mov.b64 {%0,%1}, %2;" : "=f"(a), "=f"(b) : "l"(v));
}

// Scratch (device globals; no runtime allocation)
__device__ float g_xadj[ROW_TOTAL * EMBED];      // 33.5 MB
__device__ float g_agg_adj[ROW_TOTAL * EMBED];   // 33.5 MB
__device__ float g_agg_conf[ROW_TOTAL * EMBED];  // 33.5 MB
__device__ int   g_deg[N_NODES];
__device__ int   g_rowptr[N_NODES + 1];
__device__ int   g_cursor[N_NODES];
__device__ float g_dinv[N_NODES];
__device__ int   g_csr_src[TOT_E];
__device__ float g_csr_norm[TOT_E];

// ---------------- K0: init degree with self loop ----------------
__global__ void k_init_deg() {
    int i = blockIdx.x * blockDim.x + threadIdx.x;
    if (i < N_NODES) g_deg[i] = 1;
}

// ---------------- K1: count in-degrees ----------------
__global__ void k_count(const int* __restrict__ dst) {
    int e = blockIdx.x * blockDim.x + threadIdx.x;
    if (e < N_EDGES) atomicAdd(&g_deg[dst[e]], 1);
}

// ---------------- K2: dinv + exclusive scan (single block) ----------------
__global__ void k_scan() {
    __shared__ int buf[2][N_NODES];
    int t = threadIdx.x;  // 1024 threads
    for (int k = t; k < N_NODES; k += 1024) {
        int d = g_deg[k];
        buf[0][k] = d;
        g_dinv[k] = rsqrtf((float)d);
    }
    __syncthreads();
    int cur = 0;
    for (int off = 1; off < N_NODES; off <<= 1) {
        int nxt = cur ^ 1;
        for (int k = t; k < N_NODES; k += 1024) {
            int v = buf[cur][k];
            if (k >= off) v += buf[cur][k - off];
            buf[nxt][k] = v;
        }
        __syncthreads();
        cur = nxt;
    }
    for (int k = t; k < N_NODES; k += 1024) {
        int incl = buf[cur][k];
        int excl = incl - g_deg[k];
        g_rowptr[k + 1] = incl;
        g_cursor[k] = excl;
    }
    if (t == 0) g_rowptr[0] = 0;
}

// ---------------- K3: fill CSR ----------------
__global__ void k_fill(const int* __restrict__ src, const int* __restrict__ dst) {
    int idx = blockIdx.x * blockDim.x + threadIdx.x;
    if (idx < N_EDGES) {
        int s = src[idx];
        int d = dst[idx];
        int p = atomicAdd(&g_cursor[d], 1);
        g_csr_src[p] = s;
        g_csr_norm[p] = g_dinv[s] * g_dinv[d];
    } else if (idx < TOT_E) {
        int i = idx - N_EDGES;           // self loop
        int p = atomicAdd(&g_cursor[i], 1);
        g_csr_src[p] = i;
        float di = g_dinv[i];
        g_csr_norm[p] = di * di;
    }
}

// ---------------- K4: MLP + adjustment mask (f32x2, C=8) ----------------
// 32 rows/block, 128 threads.
// Stage1 (N=128): thread = cols (t&15)*8..+7, rows (t>>4)*4..+3   (R=4, C=8)
// Stage2 (N=256): thread = cols (t&31)*8..+7, rows (t>>5)*8..+7   (R=8, C=8)
__global__ void __launch_bounds__(128) k_mlp(
    const float* __restrict__ x,
    const float* __restrict__ w1, const float* __restrict__ b1,
    const float* __restrict__ w2, const float* __restrict__ b2)
{
    __shared__ __align__(16) float xs[32][EMBED];   // 32 KB
    __shared__ __align__(16) float hs[32][HIDDEN];  // 16 KB
    const int t = threadIdx.x;
    const long rows0 = (long)blockIdx.x * 32;

    // load 32 rows of x (2048 float4)
    {
        const float4* xv = (const float4*)(x + rows0 * EMBED);
        float4* xsv = (float4*)&xs[0][0];
        #pragma unroll
        for (int i = 0; i < 16; i++) xsv[t + i * 128] = xv[t + i * 128];
    }
    __syncthreads();

    // ---- stage 1: h = relu(x @ w1 + b1) ----
    {
        const int c1 = (t & 15) * 8;
        const int r1 = (t >> 4) * 4;
        ull acc[4][4];
        {
            float4 ba = *(const float4*)&b1[c1];
            float4 bb = *(const float4*)&b1[c1 + 4];
            ull p0 = pk2(ba.x, ba.y), p1 = pk2(ba.z, ba.w);
            ull p2 = pk2(bb.x, bb.y), p3 = pk2(bb.z, bb.w);
            #pragma unroll
            for (int r = 0; r < 4; r++) {
                acc[r][0] = p0; acc[r][1] = p1; acc[r][2] = p2; acc[r][3] = p3;
            }
        }
        for (int k = 0; k < EMBED; k += 4) {
            ulonglong2 w[4][2];
            #pragma unroll
            for (int kk = 0; kk < 4; kk++) {
                w[kk][0] = *(const ulonglong2*)&w1[(k + kk) * HIDDEN + c1];
                w[kk][1] = *(const ulonglong2*)&w1[(k + kk) * HIDDEN + c1 + 4];
            }
            #pragma unroll
            for (int r = 0; r < 4; r++) {
                float4 aq = *(const float4*)&xs[r1 + r][k];
                ull a0 = pk2(aq.x, aq.x);
                ull a1 = pk2(aq.y, aq.y);
                ull a2 = pk2(aq.z, aq.z);
                ull a3 = pk2(aq.w, aq.w);
                fma2(acc[r][0], a0, w[0][0].x); fma2(acc[r][1], a0, w[0][0].y);
                fma2(acc[r][2], a0, w[0][1].x); fma2(acc[r][3], a0, w[0][1].y);
                fma2(acc[r][0], a1, w[1][0].x); fma2(acc[r][1], a1, w[1][0].y);
                fma2(acc[r][2], a1, w[1][1].x); fma2(acc[r][3], a1, w[1][1].y);
                fma2(acc[r][0], a2, w[2][0].x); fma2(acc[r][1], a2, w[2][0].y);
                fma2(acc[r][2], a2, w[2][1].x); fma2(acc[r][3], a2, w[2][1].y);
                fma2(acc[r][0], a3, w[3][0].x); fma2(acc[r][1], a3, w[3][0].y);
                fma2(acc[r][2], a3, w[3][1].x); fma2(acc[r][3], a3, w[3][1].y);
            }
        }
        #pragma unroll
        for (int r = 0; r < 4; r++) {
            float4 h0, h1;
            upk2(acc[r][0], h0.x, h0.y); upk2(acc[r][1], h0.z, h0.w);
            upk2(acc[r][2], h1.x, h1.y); upk2(acc[r][3], h1.z, h1.w);
            h0.x = fmaxf(h0.x, 0.f); h0.y = fmaxf(h0.y, 0.f);
            h0.z = fmaxf(h0.z, 0.f); h0.w = fmaxf(h0.w, 0.f);
            h1.x = fmaxf(h1.x, 0.f); h1.y = fmaxf(h1.y, 0.f);
            h1.z = fmaxf(h1.z, 0.f); h1.w = fmaxf(h1.w, 0.f);
            *(float4*)&hs[r1 + r][c1]     = h0;
            *(float4*)&hs[r1 + r][c1 + 4] = h1;
        }
    }
    __syncthreads();

    // ---- stage 2: z = h @ w2 + b2; x_adj = x / (1 + exp(z)) ----
    {
        const int c2 = (t & 31) * 8;
        const int r2 = (t >> 5) * 8;
        ull acc[8][4];
        {
            float4 ba = *(const float4*)&b2[c2];
            float4 bb = *(const float4*)&b2[c2 + 4];
            ull p0 = pk2(ba.x, ba.y), p1 = pk2(ba.z, ba.w);
            ull p2 = pk2(bb.x, bb.y), p3 = pk2(bb.z, bb.w);
            #pragma unroll
            for (int r = 0; r < 8; r++) {
                acc[r][0] = p0; acc[r][1] = p1; acc[r][2] = p2; acc[r][3] = p3;
            }
        }
        for (int k = 0; k < HIDDEN; k += 4) {
            ulonglong2 w[4][2];
            #pragma unroll
            for (int kk = 0; kk < 4; kk++) {
                w[kk][0] = *(const ulonglong2*)&w2[(k + kk) * EMBED + c2];
                w[kk][1] = *(const ulonglong2*)&w2[(k + kk) * EMBED + c2 + 4];
            }
            #pragma unroll
            for (int r = 0; r < 8; r++) {
                float4 aq = *(const float4*)&hs[r2 + r][k];
                ull a0 = pk2(aq.x, aq.x);
                ull a1 = pk2(aq.y, aq.y);
                ull a2 = pk2(aq.z, aq.z);
                ull a3 = pk2(aq.w, aq.w);
                fma2(acc[r][0], a0, w[0][0].x); fma2(acc[r][1], a0, w[0][0].y);
                fma2(acc[r][2], a0, w[0][1].x); fma2(acc[r][3], a0, w[0][1].y);
                fma2(acc[r][0], a1, w[1][0].x); fma2(acc[r][1], a1, w[1][0].y);
                fma2(acc[r][2], a1, w[1][1].x); fma2(acc[r][3], a1, w[1][1].y);
                fma2(acc[r][0], a2, w[2][0].x); fma2(acc[r][1], a2, w[2][0].y);
                fma2(acc[r][2], a2, w[2][1].x); fma2(acc[r][3], a2, w[2][1].y);
                fma2(acc[r][0], a3, w[3][0].x); fma2(acc[r][1], a3, w[3][0].y);
                fma2(acc[r][2], a3, w[3][1].x); fma2(acc[r][3], a3, w[3][1].y);
            }
        }
        #pragma unroll
        for (int r = 0; r < 8; r++) {
            long row = rows0 + r2 + r;
            float z[8];
            upk2(acc[r][0], z[0], z[1]);
            upk2(acc[r][1], z[2], z[3]);
            upk2(acc[r][2], z[4], z[5]);
            upk2(acc[r][3], z[6], z[7]);
            float4 xa = *(const float4*)&xs[r2 + r][c2];
            float4 xb = *(const float4*)&xs[r2 + r][c2 + 4];
            float4 o0, o1;
            o0.x = xa.x / (1.0f + __expf(z[0]));
            o0.y = xa.y / (1.0f + __expf(z[1]));
            o0.z = xa.z / (1.0f + __expf(z[2]));
            o0.w = xa.w / (1.0f + __expf(z[3]));
            o1.x = xb.x / (1.0f + __expf(z[4]));
            o1.y = xb.y / (1.0f + __expf(z[5]));
            o1.z = xb.z / (1.0f + __expf(z[6]));
            o1.w = xb.w / (1.0f + __expf(z[7]));
            *(float4*)&g_xadj[row * EMBED + c2]     = o0;
            *(float4*)&g_xadj[row * EMBED + c2 + 4] = o1;
        }
    }
}

// ---------------- K5: aggregation (gather-sum via CSR) ----------------
__global__ void __launch_bounds__(256) k_agg(const float* __restrict__ x)
{
    const int n = blockIdx.x;
    const int t = threadIdx.x;
    const int beg = g_rowptr[n], end = g_rowptr[n + 1];

    float4 aadj[4], ax[4];
    #pragma unroll
    for (int i = 0; i < 4; i++) {
        aadj[i] = make_float4(0.f, 0.f, 0.f, 0.f);
        ax[i]   = make_float4(0.f, 0.f, 0.f, 0.f);
    }

    for (int e = beg; e < end; e++) {
        int s = g_csr_src[e];
        float w = g_csr_norm[e];
        const float4* pa = (const float4*)(g_xadj + (long)s * VEC);
        const float4* px = (const float4*)(x      + (long)s * VEC);
        #pragma unroll
        for (int i = 0; i < 4; i++) {
            int idx = t + i * 256;
            float4 va = pa[idx];
            float4 vx = px[idx];
            aadj[i].x = fmaf(w, va.x, aadj[i].x); ax[i].x = fmaf(w, vx.x, ax[i].x);
            aadj[i].y = fmaf(w, va.y, aadj[i].y); ax[i].y = fmaf(w, vx.y, ax[i].y);
            aadj[i].z = fmaf(w, va.z, aadj[i].z); ax[i].z = fmaf(w, vx.z, ax[i].z);
            aadj[i].w = fmaf(w, va.w, aadj[i].w); ax[i].w = fmaf(w, vx.w, ax[i].w);
        }
    }

    float4* oa = (float4*)(g_agg_adj  + (long)n * VEC);
    float4* oc = (float4*)(g_agg_conf + (long)n * VEC);
    #pragma unroll
    for (int i = 0; i < 4; i++) {
        int idx = t + i * 256;
        oa[idx] = aadj[i];
        float4 c;
        c.x = ax[i].x - aadj[i].x;
        c.y = ax[i].y - aadj[i].y;
        c.z = ax[i].z - aadj[i].z;
        c.w = ax[i].w - aadj[i].w;
        oc[idx] = c;
    }
}

// ---------------- K6: output GEMM + bias (f32x2, R=8 C=8) ----------------
// grid (1024, 2); 32 rows/block, 128 threads.
// Thread = cols (t&31)*8..+7, rows (t>>5)*8..+7.
__global__ void __launch_bounds__(128) k_gemm(
    const float* __restrict__ w_adj, const float* __restrict__ b_adj,
    const float* __restrict__ w_conf, const float* __restrict__ b_conf,
    float* __restrict__ out)
{
    __shared__ __align__(16) float as[32][EMBED];   // 32 KB
    const int sel = blockIdx.y;
    const float* A = sel ? g_agg_conf : g_agg_adj;
    const float* W = sel ? w_conf : w_adj;
    const float* Bb = sel ? b_conf : b_adj;
    float* O = out + (long)sel * ((long)ROW_TOTAL * EMBED);

    const int t = threadIdx.x;
    const long rows0 = (long)blockIdx.x * 32;

    {
        const float4* av = (const float4*)(A + rows0 * EMBED);
        float4* asv = (float4*)&as[0][0];
        #pragma unroll
        for (int i = 0; i < 16; i++) asv[t + i * 128] = av[t + i * 128];
    }
    __syncthreads();

    const int c  = (t & 31) * 8;
    const int r0 = (t >> 5) * 8;

    ull acc[8][4];
    {
        float4 ba = *(const float4*)&Bb[c];
        float4 bb = *(const float4*)&Bb[c + 4];
        ull p0 = pk2(ba.x, ba.y), p1 = pk2(ba.z, ba.w);
        ull p2 = pk2(bb.x, bb.y), p3 = pk2(bb.z, bb.w);
        #pragma unroll
        for (int r = 0; r < 8; r++) {
            acc[r][0] = p0; acc[r][1] = p1; acc[r][2] = p2; acc[r][3] = p3;
        }
    }

    for (int k = 0; k < EMBED; k += 4) {
        ulonglong2 w[4][2];
        #pragma unroll
        for (int kk = 0; kk < 4; kk++) {
            w[kk][0] = *(const ulonglong2*)&W[(k + kk) * EMBED + c];
            w[kk][1] = *(const ulonglong2*)&W[(k + kk) * EMBED + c + 4];
        }
        #pragma unroll
        for (int r = 0; r < 8; r++) {
            float4 aq = *(const float4*)&as[r0 + r][k];
            ull a0 = pk2(aq.x, aq.x);
            ull a1 = pk2(aq.y, aq.y);
            ull a2 = pk2(aq.z, aq.z);
            ull a3 = pk2(aq.w, aq.w);
            fma2(acc[r][0], a0, w[0][0].x); fma2(acc[r][1], a0, w[0][0].y);
            fma2(acc[r][2], a0, w[0][1].x); fma2(acc[r][3], a0, w[0][1].y);
            fma2(acc[r][0], a1, w[1][0].x); fma2(acc[r][1], a1, w[1][0].y);
            fma2(acc[r][2], a1, w[1][1].x); fma2(acc[r][3], a1, w[1][1].y);
            fma2(acc[r][0], a2, w[2][0].x); fma2(acc[r][1], a2, w[2][0].y);
            fma2(acc[r][2], a2, w[2][1].x); fma2(acc[r][3], a2, w[2][1].y);
            fma2(acc[r][0], a3, w[3][0].x); fma2(acc[r][1], a3, w[3][0].y);
            fma2(acc[r][2], a3, w[3][1].x); fma2(acc[r][3], a3, w[3][1].y);
        }
    }

    #pragma unroll
    for (int r = 0; r < 8; r++) {
        float4 o0, o1;
        upk2(acc[r][0], o0.x, o0.y); upk2(acc[r][1], o0.z, o0.w);
        upk2(acc[r][2], o1.x, o1.y); upk2(acc[r][3], o1.z, o1.w);
        *(float4*)&O[(rows0 + r0 + r) * EMBED + c]     = o0;
        *(float4*)&O[(rows0 + r0 + r) * EMBED + c + 4] = o1;
    }
}

// ---------------- launch ----------------
extern "C" void kernel_launch(void* const* d_in, const int* in_sizes, int n_in,
                              void* d_out, int out_size)
{
    const float* x      = (const float*)d_in[0];
    const int*   ei     = (const int*)d_in[1];     // [2, 32768]: row0 = src, row1 = dst
    const float* w1     = (const float*)d_in[2];
    const float* b1     = (const float*)d_in[3];
    const float* w2     = (const float*)d_in[4];
    const float* b2     = (const float*)d_in[5];
    const float* w_adj  = (const float*)d_in[6];
    const float* b_adj  = (const float*)d_in[7];
    const float* w_conf = (const float*)d_in[8];
    const float* b_conf = (const float*)d_in[9];
    float* out = (float*)d_out;

    const int* src = ei;
    const int* dst = ei + N_EDGES;

    // k_mlp at launch index 3 so ncu (-s 5) captures it.
    k_init_deg<<<(N_NODES + 255) / 256, 256>>>();
    k_count<<<(N_EDGES + 255) / 256, 256>>>(dst);
    k_scan<<<1, 1024>>>();
    k_mlp<<<ROW_TOTAL / 32, 128>>>(x, w1, b1, w2, b2);
    k_fill<<<(TOT_E + 255) / 256, 256>>>(src, dst);
    k_agg<<<N_NODES, 256>>>(x);
    dim3 gg(ROW_TOTAL / 32, 2);
    k_gemm<<<gg, 128>>>(w_adj, b_adj, w_conf, b_conf, out);
}